// round 4
// baseline (speedup 1.0000x reference)
#include <cuda_runtime.h>
#include <cstdint>

// ---------------------------------------------------------------------------
// SimpleSNN: B=4096, D_in=784, H=800, D_out=10, T=32
//   u      = threefry-uniform(key=42) — partitionable stream: counter (0, f),
//            32-bit output = out0 ^ out1 (XOR of both threefry output words)
//   xf     = (u < x)                      (binary, bit-packed)
//   cur1   = xf @ W1^T + b1               (sequential-k fp32 fma chains)
//   spk1[t]= IF-neuron raster over 32 steps (layer 1 independent of layer 2)
//   cur2   = spk1 @ W2^T + b2             (batched over t, sequential-h chains)
//   out    = layer-2 IF scan spike counts
// ---------------------------------------------------------------------------

#define B_     4096
#define DIN    784
#define H_     800
#define DOUT   10
#define TSTEPS 32
#define NW     25                  // 800 bits holds the 784 bits per row

__device__ unsigned g_xbits[B_ * NW];                 // encoded input bits
__device__ float    g_cur1[B_ * H_];                  // fc1 currents
__device__ unsigned g_spk[TSTEPS * B_ * NW];          // layer-1 spike raster
__device__ float    g_cur2[TSTEPS * B_ * DOUT];       // fc2 currents per step

// ------------------------------- f32x2 helpers -----------------------------
__device__ __forceinline__ unsigned long long pack2(float lo, float hi) {
    unsigned long long d;
    asm("mov.b64 %0, {%1, %2};" : "=l"(d) : "f"(lo), "f"(hi));
    return d;
}
__device__ __forceinline__ void unpack2(unsigned long long v, float &lo, float &hi) {
    asm("mov.b64 {%0, %1}, %2;" : "=f"(lo), "=f"(hi) : "l"(v));
}
__device__ __forceinline__ unsigned long long fma2(unsigned long long a,
                                                   unsigned long long b,
                                                   unsigned long long c) {
    unsigned long long d;
    asm("fma.rn.f32x2 %0, %1, %2, %3;" : "=l"(d) : "l"(a), "l"(b), "l"(c));
    return d;
}

// ------------------------------- threefry ----------------------------------
#define ROTL32(x, d) (((x) << (d)) | ((x) >> (32 - (d))))

// Partitionable stream: counter pair (hi=0, lo=f); returns out0 ^ out1.
__device__ __forceinline__ unsigned threefry_xor(unsigned f) {
    const unsigned k0 = 0u, k1 = 42u;
    const unsigned k2 = 0x1BD11BDAu ^ k0 ^ k1;
    unsigned x0 = 0u + k0;     // hi(counter) = 0
    unsigned x1 = f + k1;      // lo(counter) = f
#define TF_R(r) { x0 += x1; x1 = ROTL32(x1, r); x1 ^= x0; }
    TF_R(13) TF_R(15) TF_R(26) TF_R(6)   x0 += k1; x1 += k2 + 1u;
    TF_R(17) TF_R(29) TF_R(16) TF_R(24)  x0 += k2; x1 += k0 + 2u;
    TF_R(13) TF_R(15) TF_R(26) TF_R(6)   x0 += k0; x1 += k1 + 3u;
    TF_R(17) TF_R(29) TF_R(16) TF_R(24)  x0 += k1; x1 += k2 + 4u;
    TF_R(13) TF_R(15) TF_R(26) TF_R(6)   x0 += k2; x1 += k0 + 5u;
#undef TF_R
    return x0 ^ x1;
}

// K1: Bernoulli encode. One thread per (row, word).
__global__ void __launch_bounds__(256) k_encode(const float *__restrict__ x) {
    int idx = blockIdx.x * 256 + threadIdx.x;     // 0 .. 102399
    int i = idx / NW;
    int w = idx % NW;
    int nbits = (w == NW - 1) ? 16 : 32;          // word 24: j 768..783 only
    long base = (long)i * DIN + w * 32;
    unsigned word = 0;
    for (int k = 0; k < nbits; k++) {
        long f = base + k;
        unsigned bits = threefry_xor((unsigned)f);
        float u = __uint_as_float((bits >> 9) | 0x3f800000u) - 1.0f;
        if (u < x[f]) word |= (1u << k);
    }
    g_xbits[idx] = word;
}

// K2: cur1 = xbits @ W1^T + b1.  BM=256 x BN=32 tile, 256 threads, TM=8 TN=4.
// Each output accumulated as a single sequential fp32 fma chain over j=0..783.
__global__ void __launch_bounds__(256) k_gemm1(const float *__restrict__ W1,
                                               const float *__restrict__ b1) {
    __shared__ unsigned Aw[256];
    __shared__ float Bs[32][34];                  // [jj][c], pad->8B aligned pairs
    int tid = threadIdx.x;
    int rowbase = blockIdx.x * 256;
    int colbase = blockIdx.y * 32;
    int tc = tid & 7, tr = tid >> 3;
    int c0 = tc * 4, r0 = tr * 8;
    int ldc = tid >> 3;                           // B-load: this thread's h col
    int ldj = (tid & 7) * 4;                      // and 4 consecutive j

    unsigned long long acc[8][2];
#pragma unroll
    for (int r = 0; r < 8; r++) { acc[r][0] = 0ull; acc[r][1] = 0ull; }

    for (int kw = 0; kw < NW; kw++) {
        Aw[tid] = g_xbits[(rowbase + tid) * NW + kw];
        int j = kw * 32 + ldj;
        float4 bv = make_float4(0.f, 0.f, 0.f, 0.f);
        if (j < DIN)                              // j%4==0 and DIN%4==0 -> whole vec valid
            bv = *(const float4 *)(W1 + (long)(colbase + ldc) * DIN + j);
        Bs[ldj + 0][ldc] = bv.x;
        Bs[ldj + 1][ldc] = bv.y;
        Bs[ldj + 2][ldc] = bv.z;
        Bs[ldj + 3][ldc] = bv.w;
        __syncthreads();

        unsigned a[8];
#pragma unroll
        for (int r = 0; r < 8; r++) a[r] = Aw[r0 + r];

#pragma unroll
        for (int jj = 0; jj < 32; jj++) {
            unsigned long long b01 = *(const unsigned long long *)&Bs[jj][c0];
            unsigned long long b23 = *(const unsigned long long *)&Bs[jj][c0 + 2];
#pragma unroll
            for (int r = 0; r < 8; r++) {
                float s = ((a[r] >> jj) & 1u) ? 1.0f : 0.0f;
                unsigned long long ss = pack2(s, s);
                acc[r][0] = fma2(ss, b01, acc[r][0]);
                acc[r][1] = fma2(ss, b23, acc[r][1]);
            }
        }
        __syncthreads();
    }

    float bb0 = b1[colbase + c0 + 0];
    float bb1 = b1[colbase + c0 + 1];
    float bb2 = b1[colbase + c0 + 2];
    float bb3 = b1[colbase + c0 + 3];
#pragma unroll
    for (int r = 0; r < 8; r++) {
        int row = rowbase + r0 + r;
        float o0, o1, o2, o3;
        unpack2(acc[r][0], o0, o1);
        unpack2(acc[r][1], o2, o3);
        float4 out = make_float4(o0 + bb0, o1 + bb1, o2 + bb2, o3 + bb3);
        *(float4 *)(g_cur1 + (long)row * H_ + colbase + c0) = out;
    }
}

// K3: layer-1 IF dynamics -> packed spike raster. One warp per (row, word).
__global__ void __launch_bounds__(256) k_spikegen() {
    int gtid = blockIdx.x * 256 + threadIdx.x;
    int wid  = gtid >> 5;                         // 0 .. 102399
    int lane = gtid & 31;
    int i = wid / NW;
    int w = wid % NW;
    float c = g_cur1[(long)i * H_ + w * 32 + lane];
    float v = 0.0f;
#pragma unroll
    for (int t = 0; t < TSTEPS; t++) {
        float h1 = v + c;
        bool s = (h1 >= 1.0f);
        unsigned m = __ballot_sync(0xffffffffu, s);
        if (lane == 0) g_spk[(long)t * (B_ * NW) + i * NW + w] = m;
        v = s ? 0.0f : h1;
    }
}

// K4: cur2[t,i,:] = spk1[t,i,:] @ W2^T + b2. Thread owns 4 (t,i) rows; rows
// paired into f32x2 lanes (each lane = independent sequential-h chain).
__global__ void __launch_bounds__(128) k_gemm2(const float *__restrict__ W2,
                                               const float *__restrict__ b2) {
    extern __shared__ unsigned long long W2d[];   // 8000 duplicated-pair weights
    for (int j = threadIdx.x; j < DOUT * H_; j += 128) {
        float wv = W2[j];
        W2d[j] = pack2(wv, wv);
    }
    __syncthreads();

    int gid = blockIdx.x * 128 + threadIdx.x;     // 0 .. 32767
    long row0 = (long)0 * 32768 + gid;
    long row1 = (long)1 * 32768 + gid;
    long row2 = (long)2 * 32768 + gid;
    long row3 = (long)3 * 32768 + gid;

    unsigned long long acc0[DOUT], acc1[DOUT];
#pragma unroll
    for (int o = 0; o < DOUT; o++) { acc0[o] = 0ull; acc1[o] = 0ull; }

    for (int w = 0; w < NW; w++) {
        unsigned wd0 = g_spk[row0 * NW + w];
        unsigned wd1 = g_spk[row1 * NW + w];
        unsigned wd2 = g_spk[row2 * NW + w];
        unsigned wd3 = g_spk[row3 * NW + w];
        int hbase = w * 32;
#pragma unroll
        for (int k = 0; k < 32; k++) {
            float s0 = ((wd0 >> k) & 1u) ? 1.0f : 0.0f;
            float s1 = ((wd1 >> k) & 1u) ? 1.0f : 0.0f;
            float s2 = ((wd2 >> k) & 1u) ? 1.0f : 0.0f;
            float s3 = ((wd3 >> k) & 1u) ? 1.0f : 0.0f;
            unsigned long long s01 = pack2(s0, s1);
            unsigned long long s23 = pack2(s2, s3);
            int h = hbase + k;
#pragma unroll
            for (int o = 0; o < DOUT; o++) {
                unsigned long long ww = W2d[o * H_ + h];
                acc0[o] = fma2(s01, ww, acc0[o]);
                acc1[o] = fma2(s23, ww, acc1[o]);
            }
        }
    }

#pragma unroll
    for (int o = 0; o < DOUT; o++) {
        float bo = b2[o];
        float a, b;
        unpack2(acc0[o], a, b);
        g_cur2[row0 * DOUT + o] = a + bo;
        g_cur2[row1 * DOUT + o] = b + bo;
        unpack2(acc1[o], a, b);
        g_cur2[row2 * DOUT + o] = a + bo;
        g_cur2[row3 * DOUT + o] = b + bo;
    }
}

// K5: layer-2 IF scan -> spike counts. One thread per (i, o).
__global__ void __launch_bounds__(256) k_scan(float *__restrict__ out) {
    int id = blockIdx.x * 256 + threadIdx.x;      // 0 .. 40959
    int i = id / DOUT;
    int o = id % DOUT;
    float v = 0.0f, cnt = 0.0f;
#pragma unroll
    for (int t = 0; t < TSTEPS; t++) {
        float c2 = g_cur2[((long)t * B_ + i) * DOUT + o];
        float h2 = v + c2;
        bool s = (h2 >= 1.0f);
        cnt += s ? 1.0f : 0.0f;
        v = s ? 0.0f : h2;
    }
    out[id] = cnt;
}

// ---------------------------------------------------------------------------
extern "C" void kernel_launch(void *const *d_in, const int *in_sizes, int n_in,
                              void *d_out, int out_size) {
    const float *x  = (const float *)d_in[0];
    const float *W1 = (const float *)d_in[1];
    const float *b1 = (const float *)d_in[2];
    const float *W2 = (const float *)d_in[3];
    const float *b2 = (const float *)d_in[4];
    float *out = (float *)d_out;

    // K1: 4096*25 = 102400 threads
    k_encode<<<400, 256>>>(x);

    // K2: grid (4096/256, 800/32)
    k_gemm1<<<dim3(16, 25), 256>>>(W1, b1);

    // K3: 102400 warps
    k_spikegen<<<12800, 256>>>();

    // K4: 32768 threads, 4 rows each; 64000B dynamic smem (dup W2 pairs)
    cudaFuncSetAttribute(k_gemm2, cudaFuncAttributeMaxDynamicSharedMemorySize,
                         DOUT * H_ * (int)sizeof(unsigned long long));
    k_gemm2<<<256, 128, DOUT * H_ * sizeof(unsigned long long)>>>(W2, b2);

    // K5: 40960 threads
    k_scan<<<160, 256>>>(out);
}

// round 5
// speedup vs baseline: 1.0179x; 1.0179x over previous
#include <cuda_runtime.h>
#include <cstdint>

// ---------------------------------------------------------------------------
// SimpleSNN: B=4096, D_in=784, H=800, D_out=10, T=32
//   u      = threefry-uniform(key=42) — partitionable stream: counter (0, f),
//            32-bit output = out0 ^ out1
//   xf     = (u < x)                      (binary, bit-packed)
//   cur1   = xf @ W1^T + b1               (sequential-k fp32 fma chains)
//   spk1[t]= IF-neuron raster over 32 steps
//   cur2   = spk1 @ W2^T + b2             (batched over t, sequential-h chains)
//   out    = layer-2 IF scan spike counts
// NOTE: rel_err==0 requires every per-output accumulation chain to keep its
// exact sequential k/h order. Lane-pairing may change; chain order may not.
// ---------------------------------------------------------------------------

#define B_     4096
#define DIN    784
#define H_     800
#define DOUT   10
#define TSTEPS 32
#define NW     25

__device__ unsigned g_xbits[B_ * NW];
__device__ float    g_cur1[B_ * H_];
__device__ unsigned g_spk[TSTEPS * B_ * NW];
__device__ float    g_cur2[TSTEPS * B_ * DOUT];

// ------------------------------- f32x2 helpers -----------------------------
__device__ __forceinline__ unsigned long long pack2(float lo, float hi) {
    unsigned long long d;
    asm("mov.b64 %0, {%1, %2};" : "=l"(d) : "f"(lo), "f"(hi));
    return d;
}
__device__ __forceinline__ void unpack2(unsigned long long v, float &lo, float &hi) {
    asm("mov.b64 {%0, %1}, %2;" : "=f"(lo), "=f"(hi) : "l"(v));
}
__device__ __forceinline__ unsigned long long fma2(unsigned long long a,
                                                   unsigned long long b,
                                                   unsigned long long c) {
    unsigned long long d;
    asm("fma.rn.f32x2 %0, %1, %2, %3;" : "=l"(d) : "l"(a), "l"(b), "l"(c));
    return d;
}

// ------------------------------- threefry ----------------------------------
#define ROTL32(x, d) (((x) << (d)) | ((x) >> (32 - (d))))

__device__ __forceinline__ unsigned threefry_xor(unsigned f) {
    const unsigned k0 = 0u, k1 = 42u;
    const unsigned k2 = 0x1BD11BDAu ^ k0 ^ k1;
    unsigned x0 = 0u + k0;
    unsigned x1 = f + k1;
#define TF_R(r) { x0 += x1; x1 = ROTL32(x1, r); x1 ^= x0; }
    TF_R(13) TF_R(15) TF_R(26) TF_R(6)   x0 += k1; x1 += k2 + 1u;
    TF_R(17) TF_R(29) TF_R(16) TF_R(24)  x0 += k2; x1 += k0 + 2u;
    TF_R(13) TF_R(15) TF_R(26) TF_R(6)   x0 += k0; x1 += k1 + 3u;
    TF_R(17) TF_R(29) TF_R(16) TF_R(24)  x0 += k1; x1 += k2 + 4u;
    TF_R(13) TF_R(15) TF_R(26) TF_R(6)   x0 += k2; x1 += k0 + 5u;
#undef TF_R
    return x0 ^ x1;
}

// K1: Bernoulli encode. One thread per (row, word).
__global__ void __launch_bounds__(256) k_encode(const float *__restrict__ x) {
    int idx = blockIdx.x * 256 + threadIdx.x;
    int i = idx / NW;
    int w = idx % NW;
    int nbits = (w == NW - 1) ? 16 : 32;
    long base = (long)i * DIN + w * 32;
    unsigned word = 0;
    for (int k = 0; k < nbits; k++) {
        long f = base + k;
        unsigned bits = threefry_xor((unsigned)f);
        float u = __uint_as_float((bits >> 9) | 0x3f800000u) - 1.0f;
        if (u < x[f]) word |= (1u << k);
    }
    g_xbits[idx] = word;
}

// K2: cur1 = xbits @ W1^T + b1.  BM=256 x BN=32 tile, 128 threads, TM=8 TN=8.
// Each output is one sequential fp32 fma chain over j=0..783 (order preserved).
__global__ void __launch_bounds__(128) k_gemm1(const float *__restrict__ W1,
                                               const float *__restrict__ b1) {
    __shared__ unsigned Aw[256];
    __shared__ float Bs[32][34];                  // [jj][c]; stride 34 keeps 8B pairs aligned
    int tid = threadIdx.x;
    int rowbase = blockIdx.x * 256;
    int colbase = blockIdx.y * 32;
    int tc = tid & 3, tr = tid >> 2;              // 4 col-groups x 32 row-groups
    int c0 = tc * 8, r0 = tr * 8;

    unsigned long long acc[8][4];
#pragma unroll
    for (int r = 0; r < 8; r++)
#pragma unroll
        for (int q = 0; q < 4; q++) acc[r][q] = 0ull;

    for (int kw = 0; kw < NW; kw++) {
        Aw[tid]       = g_xbits[(rowbase + tid) * NW + kw];
        Aw[tid + 128] = g_xbits[(rowbase + tid + 128) * NW + kw];
#pragma unroll
        for (int q = 0; q < 2; q++) {
            int l = tid * 2 + q;                  // 0..255 vec4 slots
            int c = l >> 3;                       // 0..31
            int jv = (l & 7) * 4;                 // 0,4,..28
            int j = kw * 32 + jv;
            float4 bv = make_float4(0.f, 0.f, 0.f, 0.f);
            if (j < DIN)
                bv = *(const float4 *)(W1 + (long)(colbase + c) * DIN + j);
            Bs[jv + 0][c] = bv.x;
            Bs[jv + 1][c] = bv.y;
            Bs[jv + 2][c] = bv.z;
            Bs[jv + 3][c] = bv.w;
        }
        __syncthreads();

        unsigned a[8];
#pragma unroll
        for (int r = 0; r < 8; r++) a[r] = Aw[r0 + r];

#pragma unroll
        for (int jj = 0; jj < 32; jj++) {
            unsigned long long b01 = *(const unsigned long long *)&Bs[jj][c0];
            unsigned long long b23 = *(const unsigned long long *)&Bs[jj][c0 + 2];
            unsigned long long b45 = *(const unsigned long long *)&Bs[jj][c0 + 4];
            unsigned long long b67 = *(const unsigned long long *)&Bs[jj][c0 + 6];
#pragma unroll
            for (int r = 0; r < 8; r++) {
                float s = ((a[r] >> jj) & 1u) ? 1.0f : 0.0f;
                unsigned long long ss = pack2(s, s);
                acc[r][0] = fma2(ss, b01, acc[r][0]);
                acc[r][1] = fma2(ss, b23, acc[r][1]);
                acc[r][2] = fma2(ss, b45, acc[r][2]);
                acc[r][3] = fma2(ss, b67, acc[r][3]);
            }
        }
        __syncthreads();
    }

    float bb[8];
#pragma unroll
    for (int q = 0; q < 8; q++) bb[q] = b1[colbase + c0 + q];
#pragma unroll
    for (int r = 0; r < 8; r++) {
        int row = rowbase + r0 + r;
        float o0, o1, o2, o3, o4, o5, o6, o7;
        unpack2(acc[r][0], o0, o1);
        unpack2(acc[r][1], o2, o3);
        unpack2(acc[r][2], o4, o5);
        unpack2(acc[r][3], o6, o7);
        float4 lo = make_float4(o0 + bb[0], o1 + bb[1], o2 + bb[2], o3 + bb[3]);
        float4 hi = make_float4(o4 + bb[4], o5 + bb[5], o6 + bb[6], o7 + bb[7]);
        *(float4 *)(g_cur1 + (long)row * H_ + colbase + c0)     = lo;
        *(float4 *)(g_cur1 + (long)row * H_ + colbase + c0 + 4) = hi;
    }
}

// K3: layer-1 IF dynamics -> packed spike raster. One warp per (row, word).
__global__ void __launch_bounds__(256) k_spikegen() {
    int gtid = blockIdx.x * 256 + threadIdx.x;
    int wid  = gtid >> 5;
    int lane = gtid & 31;
    int i = wid / NW;
    int w = wid % NW;
    float c = g_cur1[(long)i * H_ + w * 32 + lane];
    float v = 0.0f;
#pragma unroll
    for (int t = 0; t < TSTEPS; t++) {
        float h1 = v + c;
        bool s = (h1 >= 1.0f);
        unsigned m = __ballot_sync(0xffffffffu, s);
        if (lane == 0) g_spk[(long)t * (B_ * NW) + i * NW + w] = m;
        v = s ? 0.0f : h1;
    }
}

// K4: cur2 = spk1 @ W2^T + b2. One thread = 2 (t,i) rows (one f32x2 pair) ->
// 65536 threads for occupancy. h-chain order per row unchanged (w outer, k inner).
__global__ void __launch_bounds__(256) k_gemm2(const float *__restrict__ W2,
                                               const float *__restrict__ b2) {
    extern __shared__ unsigned long long W2d[];   // 8000 duplicated-pair weights
    for (int j = threadIdx.x; j < DOUT * H_; j += 256) {
        float wv = W2[j];
        W2d[j] = pack2(wv, wv);
    }
    __syncthreads();

    int gid = blockIdx.x * 256 + threadIdx.x;     // 0 .. 65535
    long row0 = (long)gid;
    long row1 = (long)gid + 65536;

    unsigned long long acc[DOUT];
#pragma unroll
    for (int o = 0; o < DOUT; o++) acc[o] = 0ull;

    for (int w = 0; w < NW; w++) {
        unsigned wd0 = g_spk[row0 * NW + w];
        unsigned wd1 = g_spk[row1 * NW + w];
        int hbase = w * 32;
#pragma unroll
        for (int k = 0; k < 32; k++) {
            float s0 = ((wd0 >> k) & 1u) ? 1.0f : 0.0f;
            float s1 = ((wd1 >> k) & 1u) ? 1.0f : 0.0f;
            unsigned long long s01 = pack2(s0, s1);
            int h = hbase + k;
#pragma unroll
            for (int o = 0; o < DOUT; o++)
                acc[o] = fma2(s01, W2d[o * H_ + h], acc[o]);
        }
    }

#pragma unroll
    for (int o = 0; o < DOUT; o++) {
        float bo = b2[o];
        float a, b;
        unpack2(acc[o], a, b);
        g_cur2[row0 * DOUT + o] = a + bo;
        g_cur2[row1 * DOUT + o] = b + bo;
    }
}

// K5: layer-2 IF scan -> spike counts. One thread per (i, o).
__global__ void __launch_bounds__(256) k_scan(float *__restrict__ out) {
    int id = blockIdx.x * 256 + threadIdx.x;
    int i = id / DOUT;
    int o = id % DOUT;
    float v = 0.0f, cnt = 0.0f;
#pragma unroll
    for (int t = 0; t < TSTEPS; t++) {
        float c2 = g_cur2[((long)t * B_ + i) * DOUT + o];
        float h2 = v + c2;
        bool s = (h2 >= 1.0f);
        cnt += s ? 1.0f : 0.0f;
        v = s ? 0.0f : h2;
    }
    out[id] = cnt;
}

// ---------------------------------------------------------------------------
extern "C" void kernel_launch(void *const *d_in, const int *in_sizes, int n_in,
                              void *d_out, int out_size) {
    const float *x  = (const float *)d_in[0];
    const float *W1 = (const float *)d_in[1];
    const float *b1 = (const float *)d_in[2];
    const float *W2 = (const float *)d_in[3];
    const float *b2 = (const float *)d_in[4];
    float *out = (float *)d_out;

    k_encode<<<400, 256>>>(x);

    k_gemm1<<<dim3(16, 25), 128>>>(W1, b1);

    k_spikegen<<<12800, 256>>>();

    cudaFuncSetAttribute(k_gemm2, cudaFuncAttributeMaxDynamicSharedMemorySize,
                         DOUT * H_ * (int)sizeof(unsigned long long));
    k_gemm2<<<256, 256, DOUT * H_ * sizeof(unsigned long long)>>>(W2, b2);

    k_scan<<<160, 256>>>(out);
}